// round 1
// baseline (speedup 1.0000x reference)
#include <cuda_runtime.h>

#define BB 4
#define TT 256
#define LL 216
#define EPC 12
#define EROOT 12
#define EQUAL 16
#define KK 41
#define W_NM 0.1f
#define W_ADV 0.001f

// scratch (no cudaMalloc allowed)
__device__ float g_cs[BB][TT + 1][48];   // prefix sums, channel innermost (padded to 48)
__device__ float g_h[BB][KK][LL];        // folded harmony coefficients, k-major

// ---------------- K0: per-channel inclusive prefix sums over T ----------------
__global__ void scan_kernel(const float* __restrict__ apc,
                            const float* __restrict__ aroot,
                            const float* __restrict__ aqual,
                            const float* __restrict__ iroot,
                            const float* __restrict__ iqual) {
    int ch = blockIdx.x;   // 0..40
    int b  = blockIdx.y;   // 0..3
    int t  = threadIdx.x;  // 0..255

    float x;
    if (ch < 12) {
        x = apc[(b * TT + t) * EPC + ch];
    } else if (ch < 24) {
        int j = ch - 12;
        x = aroot[(b * TT + t) * EROOT + j] - W_ADV * iroot[(b * TT + t) * EROOT + j];
    } else if (ch < 40) {
        int j = ch - 24;
        x = aqual[(b * TT + t) * EQUAL + j] - W_ADV * iqual[(b * TT + t) * EQUAL + j];
    } else {
        x = 1.0f;   // channel 40: segment mean == 1 (carries the -W_NM*Hs term)
    }

    __shared__ float buf[TT];
    buf[t] = x;
    __syncthreads();
    #pragma unroll
    for (int off = 1; off < TT; off <<= 1) {
        float v = (t >= off) ? buf[t - off] : 0.0f;
        __syncthreads();
        buf[t] += v;
        __syncthreads();
    }
    g_cs[b][t + 1][ch] = buf[t];
    if (t == 0) g_cs[b][0][ch] = 0.0f;
}

// ---------------- K1: fold all l-dependent scalars into h[b][k][l] ----------------
__global__ void hprep_kernel(const float* __restrict__ hpc,
                             const float* __restrict__ hroot,
                             const float* __restrict__ hqual,
                             const int* __restrict__ pc_only) {
    int b = blockIdx.x;
    int l = threadIdx.x;
    if (l >= LL) return;
    int po = pc_only ? pc_only[0] : 0;

    float hv[12];
    float hs = 0.0f;
    #pragma unroll
    for (int j = 0; j < 12; j++) {
        hv[j] = hpc[(b * LL + l) * EPC + j];
        hs += hv[j];
    }
    float coef = (1.0f + 2.0f * W_NM) - W_ADV / hs;
    #pragma unroll
    for (int j = 0; j < 12; j++) g_h[b][j][l] = hv[j] * coef - W_NM;
    #pragma unroll
    for (int j = 0; j < 12; j++) g_h[b][12 + j][l] = po ? 0.0f : hroot[(b * LL + l) * EROOT + j];
    #pragma unroll
    for (int j = 0; j < 16; j++) g_h[b][24 + j][l] = po ? 0.0f : hqual[(b * LL + l) * EQUAL + j];
    g_h[b][40][l] = -W_NM * hs;
}

// ---------------- main: tiled 41-K GEMM with diagonal skip ----------------
// tile = 128 segment pairs (8 s-values x 16 e-values) x 108 l-values
// 288 threads = 16 (ts) x 18 (tl); microtile 8 (se) x 6 (l) per thread
#define TS 8
#define TE 16
#define TL 108
#define NTHR 288

__global__ __launch_bounds__(NTHR, 2)
void main_kernel(float* __restrict__ out) {
    __shared__ float ms[KK][128];   // segment-mean tile, k-major
    __shared__ float hsm[KK][TL];   // harmony tile, k-major

    const int b  = blockIdx.z;
    const int lt = blockIdx.x;              // 0..1
    const int st = blockIdx.y >> 4;         // 0..31
    const int et = blockIdx.y & 15;         // 0..15
    const int s0 = st * TS, e0 = et * TE, l0 = lt * TL;
    const int tid = threadIdx.x;

    const bool tile_valid = (e0 + TE - 1) >= s0;

    const int tl = tid % 18;
    const int ts = tid / 18;

    float acc[8][6];
    #pragma unroll
    for (int i = 0; i < 8; i++)
        #pragma unroll
        for (int j = 0; j < 6; j++) acc[i][j] = 0.0f;

    if (tile_valid) {
        // fill segment tile: m = (cs[e+1] - cs[s]) / max(len,1)
        for (int idx = tid; idx < KK * 128; idx += NTHR) {
            int k = idx >> 7;
            int r = idx & 127;
            int ls = r >> 4, le = r & 15;
            int len = (e0 + le) - (s0 + ls) + 1;
            float inv = __fdividef(1.0f, (float)max(len, 1));
            ms[k][r] = (g_cs[b][e0 + le + 1][k] - g_cs[b][s0 + ls][k]) * inv;
        }
        // fill harmony tile
        for (int idx = tid; idx < KK * TL; idx += NTHR) {
            int k = idx / TL;
            int c = idx - k * TL;
            hsm[k][c] = g_h[b][k][l0 + c];
        }
        __syncthreads();

        #pragma unroll 1
        for (int k = 0; k < KK; k++) {
            float4 m0 = *(const float4*)&ms[k][ts * 8];
            float4 m1 = *(const float4*)&ms[k][ts * 8 + 4];
            float2 h0 = *(const float2*)&hsm[k][tl * 2];
            float2 h1 = *(const float2*)&hsm[k][tl * 2 + 36];
            float2 h2 = *(const float2*)&hsm[k][tl * 2 + 72];
            float mv[8] = {m0.x, m0.y, m0.z, m0.w, m1.x, m1.y, m1.z, m1.w};
            float hv[6] = {h0.x, h0.y, h1.x, h1.y, h2.x, h2.y};
            #pragma unroll
            for (int i = 0; i < 8; i++)
                #pragma unroll
                for (int j = 0; j < 6; j++)
                    acc[i][j] = fmaf(mv[i], hv[j], acc[i][j]);
        }
    }

    // store (mask e < s to zero; poisoned output must be fully written)
    #pragma unroll
    for (int i = 0; i < 8; i++) {
        int r = ts * 8 + i;
        int s = s0 + (r >> 4);
        int e = e0 + (r & 15);
        bool valid = (e >= s);
        float* po = out + ((size_t)((b * TT + s) * TT + e)) * LL + l0 + tl * 2;
        #pragma unroll
        for (int jc = 0; jc < 3; jc++) {
            float2 v;
            v.x = valid ? acc[i][2 * jc]     : 0.0f;
            v.y = valid ? acc[i][2 * jc + 1] : 0.0f;
            *(float2*)(po + 36 * jc) = v;
        }
    }
}

extern "C" void kernel_launch(void* const* d_in, const int* in_sizes, int n_in,
                              void* d_out, int out_size) {
    const float* apc   = (const float*)d_in[0];
    const float* aroot = (const float*)d_in[1];
    const float* aqual = (const float*)d_in[2];
    // d_in[3] = inactive_pc: unused by the reference
    const float* iroot = (const float*)d_in[4];
    const float* iqual = (const float*)d_in[5];
    const float* hpc   = (const float*)d_in[6];
    const float* hroot = (const float*)d_in[7];
    const float* hqual = (const float*)d_in[8];
    const int*   pco   = (n_in > 9) ? (const int*)d_in[9] : nullptr;

    scan_kernel<<<dim3(KK, BB), TT>>>(apc, aroot, aqual, iroot, iqual);
    hprep_kernel<<<BB, 256>>>(hpc, hroot, hqual, pco);
    main_kernel<<<dim3(2, 512, BB), NTHR>>>((float*)d_out);
}